// round 3
// baseline (speedup 1.0000x reference)
#include <cuda_runtime.h>

// DopamineArea: out_spikes = (spikes >= 0.5), S = mean(out_spikes), delta = S - P.
// d_out layout: [delta (N floats), out_spikes (N floats)].

#define N_TOTAL 33554432
#define THRESH 0.5f

__device__ unsigned long long g_spike_count;

__global__ void reset_count_kernel() {
    g_spike_count = 0ULL;
}

// Pass 1: spikes -> out_spikes, accumulate exact integer count of firing neurons.
__global__ void __launch_bounds__(256) spike_count_kernel(
    const float4* __restrict__ spikes4,
    float4* __restrict__ out4,
    int n4)
{
    int i = blockIdx.x * blockDim.x + threadIdx.x;
    unsigned int c = 0;
    if (i < n4) {
        float4 s = spikes4[i];
        float4 o;
        o.x = (s.x >= THRESH) ? 1.0f : 0.0f;
        o.y = (s.y >= THRESH) ? 1.0f : 0.0f;
        o.z = (s.z >= THRESH) ? 1.0f : 0.0f;
        o.w = (s.w >= THRESH) ? 1.0f : 0.0f;
        out4[i] = o;
        c = (unsigned int)(o.x + o.y + o.z + o.w);
    }

    // warp reduce
    #pragma unroll
    for (int off = 16; off > 0; off >>= 1)
        c += __shfl_down_sync(0xFFFFFFFFu, c, off);

    __shared__ unsigned int warp_sums[8];  // 256 threads -> 8 warps
    int lane = threadIdx.x & 31;
    int wid  = threadIdx.x >> 5;
    if (lane == 0) warp_sums[wid] = c;
    __syncthreads();

    if (wid == 0) {
        unsigned int v = (lane < 8) ? warp_sums[lane] : 0u;
        #pragma unroll
        for (int off = 4; off > 0; off >>= 1)
            v += __shfl_down_sync(0xFFFFFFFFu, v, off);
        if (lane == 0 && v > 0)
            atomicAdd(&g_spike_count, (unsigned long long)v);
    }
}

// Pass 2: delta = S - P.
__global__ void __launch_bounds__(256) delta_kernel(
    const float4* __restrict__ P4,
    float4* __restrict__ delta4,
    int n4)
{
    float S = (float)((double)g_spike_count / (double)N_TOTAL);
    int i = blockIdx.x * blockDim.x + threadIdx.x;
    if (i < n4) {
        float4 p = P4[i];
        float4 d;
        d.x = S - p.x;
        d.y = S - p.y;
        d.z = S - p.z;
        d.w = S - p.w;
        delta4[i] = d;
    }
}

extern "C" void kernel_launch(void* const* d_in, const int* in_sizes, int n_in,
                              void* d_out, int out_size)
{
    const float* spikes = (const float*)d_in[0];
    const float* P      = (const float*)d_in[1];
    float* out = (float*)d_out;

    int n  = in_sizes[0];          // 33554432
    int n4 = n >> 2;               // float4 elements

    float* delta_out  = out;       // first N floats
    float* spikes_out = out + n;   // second N floats

    const int T = 256;
    int blocks = (n4 + T - 1) / T;

    reset_count_kernel<<<1, 1>>>();
    spike_count_kernel<<<blocks, T>>>(
        (const float4*)spikes, (float4*)spikes_out, n4);
    delta_kernel<<<blocks, T>>>(
        (const float4*)P, (float4*)delta_out, n4);
}

// round 6
// speedup vs baseline: 1.4178x; 1.4178x over previous
#include <cuda_runtime.h>

// DopamineArea: out_spikes = (spikes >= 0.5), S = mean(out_spikes), delta = S - P.
// d_out layout: [delta (N floats), out_spikes (N floats)].
//
// 2-node graph:
//   node 1: spikes -> out_spikes, per-block exact spike count -> g_partials[block] (overwrite)
//   node 2: reduce g_partials (L2-resident) -> S, then delta = S - P
// No reset kernel needed: partials are fully overwritten each replay.

#define THRESH 0.5f
#define NBLOCKS 4096
#define NTHREADS 256
#define ELEMS_PT 8   // float4s per thread

__device__ unsigned int g_partials[NBLOCKS];

__global__ void __launch_bounds__(NTHREADS) spike_count_kernel(
    const float4* __restrict__ spikes4,
    float4* __restrict__ out4,
    int n4)
{
    const int tid    = threadIdx.x;
    const int idx0   = blockIdx.x * NTHREADS + tid;
    const int stride = NBLOCKS * NTHREADS;

    unsigned int c = 0;

    // 8 independent streaming loads in flight (MLP=8), streaming hints (no reuse).
    #pragma unroll
    for (int j = 0; j < ELEMS_PT; j++) {
        int i = idx0 + j * stride;
        if (i < n4) {
            float4 s = __ldcs(&spikes4[i]);
            float4 o;
            o.x = (s.x >= THRESH) ? 1.0f : 0.0f;
            o.y = (s.y >= THRESH) ? 1.0f : 0.0f;
            o.z = (s.z >= THRESH) ? 1.0f : 0.0f;
            o.w = (s.w >= THRESH) ? 1.0f : 0.0f;
            __stcs(&out4[i], o);
            c += (unsigned int)(o.x + o.y + o.z + o.w);
        }
    }

    // warp reduce
    #pragma unroll
    for (int off = 16; off > 0; off >>= 1)
        c += __shfl_down_sync(0xFFFFFFFFu, c, off);

    __shared__ unsigned int warp_sums[NTHREADS / 32];
    int lane = tid & 31;
    int wid  = tid >> 5;
    if (lane == 0) warp_sums[wid] = c;
    __syncthreads();

    if (wid == 0) {
        unsigned int v = (lane < (NTHREADS / 32)) ? warp_sums[lane] : 0u;
        #pragma unroll
        for (int off = 4; off > 0; off >>= 1)
            v += __shfl_down_sync(0xFFFFFFFFu, v, off);
        if (lane == 0) g_partials[blockIdx.x] = v;  // plain store (L2-visible next node)
    }
}

__global__ void __launch_bounds__(NTHREADS) delta_kernel(
    const float4* __restrict__ P4,
    float4* __restrict__ delta4,
    int n4, float inv_n)
{
    const int tid = threadIdx.x;

    // --- per-block redundant reduction of the 4096 partials (16 KB, L2-hit) ---
    unsigned int c = 0;
    #pragma unroll
    for (int j = 0; j < NBLOCKS / NTHREADS; j++)     // 16 loads, independent
        c += g_partials[tid + j * NTHREADS];

    #pragma unroll
    for (int off = 16; off > 0; off >>= 1)
        c += __shfl_down_sync(0xFFFFFFFFu, c, off);

    __shared__ unsigned int warp_sums[NTHREADS / 32];
    __shared__ float s_S;
    int lane = tid & 31;
    int wid  = tid >> 5;
    if (lane == 0) warp_sums[wid] = c;
    __syncthreads();
    if (tid == 0) {
        unsigned int total = 0;
        #pragma unroll
        for (int w = 0; w < NTHREADS / 32; w++) total += warp_sums[w];
        s_S = (float)total * inv_n;                  // total < 2^24 -> exact in fp32
    }
    __syncthreads();
    const float S = s_S;

    // --- streaming delta = S - P ---
    const int idx0   = blockIdx.x * NTHREADS + tid;
    const int stride = NBLOCKS * NTHREADS;
    #pragma unroll
    for (int j = 0; j < ELEMS_PT; j++) {
        int i = idx0 + j * stride;
        if (i < n4) {
            float4 p = __ldcs(&P4[i]);
            float4 d;
            d.x = S - p.x;
            d.y = S - p.y;
            d.z = S - p.z;
            d.w = S - p.w;
            __stcs(&delta4[i], d);
        }
    }
}

extern "C" void kernel_launch(void* const* d_in, const int* in_sizes, int n_in,
                              void* d_out, int out_size)
{
    const float* spikes = (const float*)d_in[0];
    const float* P      = (const float*)d_in[1];
    float* out = (float*)d_out;

    int n  = in_sizes[0];      // 33554432
    int n4 = n >> 2;           // 8388608 float4s = NBLOCKS*NTHREADS*ELEMS_PT exactly

    float* delta_out  = out;       // [0, n)
    float* spikes_out = out + n;   // [n, 2n)

    float inv_n = 1.0f / (float)n;

    spike_count_kernel<<<NBLOCKS, NTHREADS>>>(
        (const float4*)spikes, (float4*)spikes_out, n4);
    delta_kernel<<<NBLOCKS, NTHREADS>>>(
        (const float4*)P, (float4*)delta_out, n4, inv_n);
}